// round 7
// baseline (speedup 1.0000x reference)
#include <cuda_runtime.h>
#include <cstdint>
#include <math.h>

// Problem dims
#define NB   64
#define SEQ  512
#define IMG  3200
#define FC   64
#define HID  256
#define G4   1024

// Output layout (floats): [logprobs 64*512*2 | output_feats 64*512*256 | selected 64*256]
#define OFF_LP  0
#define OFF_OF  (NB*SEQ*2)
#define OFF_SEL (OFF_OF + NB*SEQ*HID)

// ---------------- scratch ----------------
__device__ float g_emb[NB * FC];
__device__ float g_fuse[NB * SEQ * FC];
__device__ float g_gx[(size_t)NB * SEQ * G4];
// LSTM cross-CTA state through L2 (no clusters, no DSMEM):
__device__ float g_h[16][2][4][256];     // [cluster][buf][batch][unit]
__device__ int   g_flags[16][SEQ];       // per-step arrival counters (target 128)

// ---------------- helpers ----------------
__device__ __forceinline__ float2 ffma2(float2 a, float2 b, float2 c) {
    unsigned long long ua = *reinterpret_cast<unsigned long long*>(&a);
    unsigned long long ub = *reinterpret_cast<unsigned long long*>(&b);
    unsigned long long uc = *reinterpret_cast<unsigned long long*>(&c);
    unsigned long long ud;
    asm("fma.rn.f32x2 %0, %1, %2, %3;" : "=l"(ud) : "l"(ua), "l"(ub), "l"(uc));
    return *reinterpret_cast<float2*>(&ud);
}

__device__ __forceinline__ float sigm(float x)  { return 1.0f / (1.0f + __expf(-x)); }
__device__ __forceinline__ float tanh_(float x) { return 1.0f - 2.0f / (__expf(2.0f * x) + 1.0f); }

__device__ __forceinline__ int ld_acquire_gpu(const int* p) {
    int v;
    asm volatile("ld.acquire.gpu.global.u32 %0, [%1];" : "=r"(v) : "l"(p) : "memory");
    return v;
}
__device__ __forceinline__ void red_release_gpu_add(int* p, int v) {
    asm volatile("red.release.gpu.global.add.u32 [%0], %1;" :: "l"(p), "r"(v) : "memory");
}

// ---------------- kernel 0: zero the flags (every launch; graph-safe) ----------------
__global__ void zero_flags_kernel() {
    ((int*)g_flags)[blockIdx.x * 512 + threadIdx.x] = 0;
}

// ---------------- kernel 1: emb ----------------
__global__ void emb_kernel(const float* __restrict__ phr,
                           const float* __restrict__ Wp,
                           const float* __restrict__ bp) {
    __shared__ float ps[304];
    int b = blockIdx.x, tid = threadIdx.x;
    for (int i = tid; i < 300; i += 64) ps[i] = phr[b * 300 + i];
    __syncthreads();
    float acc = bp[tid];
#pragma unroll 4
    for (int k = 0; k < 300; k++) acc += ps[k] * Wp[k * 64 + tid];
    g_emb[b * 64 + tid] = fmaxf(acc, 0.0f);
}

// ---------------- kernel 2: fuse ----------------
__global__ __launch_bounds__(256) void fuse_kernel(const float* __restrict__ img,
                                                   const float* __restrict__ Wc,
                                                   const float* __restrict__ bc) {
    __shared__ float As[2][16][132];
    __shared__ float Bs[2][16][64];
    __shared__ float es[64];

    const int tid = threadIdx.x;
    const int tx = tid & 15, ty = tid >> 4;
    const int row0 = blockIdx.x * 128;
    const int batch = row0 >> 9;

    if (tid < 64) es[tid] = g_emb[batch * 64 + tid];

    float bcr[4];
#pragma unroll
    for (int c = 0; c < 4; c++) bcr[c] = bc[tx * 4 + c];

    float2 acc[4][4];
#pragma unroll
    for (int mp = 0; mp < 4; mp++)
#pragma unroll
        for (int c = 0; c < 4; c++) acc[mp][c] = make_float2(0.f, 0.f);

    auto loadA = [&](int s, int kk) {
#pragma unroll
        for (int i = 0; i < 2; i++) {
            int id = tid * 2 + i;
            int m = id >> 2, q = id & 3;
            float4 v = *reinterpret_cast<const float4*>(img + (size_t)(row0 + m) * IMG + kk + q * 4);
            As[s][q * 4 + 0][m] = v.x;
            As[s][q * 4 + 1][m] = v.y;
            As[s][q * 4 + 2][m] = v.z;
            As[s][q * 4 + 3][m] = v.w;
        }
    };
    auto loadB = [&](int s, int kk) {
        int k = tid >> 4, q = tid & 15;
        *reinterpret_cast<float4*>(&Bs[s][k][q * 4]) =
            *reinterpret_cast<const float4*>(Wc + (size_t)(kk + k) * 64 + q * 4);
    };

    loadA(0, 0);
    loadB(0, 0);
    __syncthreads();

    for (int ch = 0; ch < 200; ch++) {
        int s = ch & 1;
        if (ch + 1 < 200) { loadA(s ^ 1, (ch + 1) * 16); loadB(s ^ 1, (ch + 1) * 16); }
#pragma unroll
        for (int k = 0; k < 16; k++) {
            float4 b4 = *reinterpret_cast<const float4*>(&Bs[s][k][tx * 4]);
            float4 a0 = *reinterpret_cast<const float4*>(&As[s][k][ty * 8]);
            float4 a1 = *reinterpret_cast<const float4*>(&As[s][k][ty * 8 + 4]);
            float2 aa[4] = { {a0.x, a0.y}, {a0.z, a0.w}, {a1.x, a1.y}, {a1.z, a1.w} };
            float  bb[4] = { b4.x, b4.y, b4.z, b4.w };
#pragma unroll
            for (int c = 0; c < 4; c++) {
                float2 bv = make_float2(bb[c], bb[c]);
#pragma unroll
                for (int mp = 0; mp < 4; mp++) acc[mp][c] = ffma2(aa[mp], bv, acc[mp][c]);
            }
        }
        __syncthreads();
    }

    float sc[4];
#pragma unroll
    for (int c = 0; c < 4; c++) sc[c] = es[tx * 4 + c];

#pragma unroll
    for (int mp = 0; mp < 4; mp++) {
        float4 r0v, r1v;
        r0v.x = fmaxf(acc[mp][0].x + bcr[0], 0.f) * sc[0];
        r0v.y = fmaxf(acc[mp][1].x + bcr[1], 0.f) * sc[1];
        r0v.z = fmaxf(acc[mp][2].x + bcr[2], 0.f) * sc[2];
        r0v.w = fmaxf(acc[mp][3].x + bcr[3], 0.f) * sc[3];
        r1v.x = fmaxf(acc[mp][0].y + bcr[0], 0.f) * sc[0];
        r1v.y = fmaxf(acc[mp][1].y + bcr[1], 0.f) * sc[1];
        r1v.z = fmaxf(acc[mp][2].y + bcr[2], 0.f) * sc[2];
        r1v.w = fmaxf(acc[mp][3].y + bcr[3], 0.f) * sc[3];
        int r = row0 + ty * 8 + mp * 2;
        *reinterpret_cast<float4*>(g_fuse + (size_t)r * 64 + tx * 4)       = r0v;
        *reinterpret_cast<float4*>(g_fuse + (size_t)(r + 1) * 64 + tx * 4) = r1v;
    }
}

// ---------------- kernel 2b: gx = fuse @ W_ih + (b_ih + b_hh) ----------------
__global__ __launch_bounds__(256) void gx_kernel(const float* __restrict__ Wih,
                                                 const float* __restrict__ bih,
                                                 const float* __restrict__ bhh) {
    __shared__ float As[2][16][132];
    __shared__ float Bs[2][16][64];

    const int tid = threadIdx.x;
    const int tx = tid & 15, ty = tid >> 4;
    const int row0 = blockIdx.x * 128;
    const int n0 = blockIdx.y * 64;

    float bsr[4];
#pragma unroll
    for (int c = 0; c < 4; c++) bsr[c] = bih[n0 + tx * 4 + c] + bhh[n0 + tx * 4 + c];

    float2 acc[4][4];
#pragma unroll
    for (int mp = 0; mp < 4; mp++)
#pragma unroll
        for (int c = 0; c < 4; c++) acc[mp][c] = make_float2(0.f, 0.f);

    auto loadA = [&](int s, int kk) {
#pragma unroll
        for (int i = 0; i < 2; i++) {
            int id = tid * 2 + i;
            int m = id >> 2, q = id & 3;
            float4 v = *reinterpret_cast<const float4*>(g_fuse + (size_t)(row0 + m) * FC + kk + q * 4);
            As[s][q * 4 + 0][m] = v.x;
            As[s][q * 4 + 1][m] = v.y;
            As[s][q * 4 + 2][m] = v.z;
            As[s][q * 4 + 3][m] = v.w;
        }
    };
    auto loadB = [&](int s, int kk) {
        int k = tid >> 4, q = tid & 15;
        *reinterpret_cast<float4*>(&Bs[s][k][q * 4]) =
            *reinterpret_cast<const float4*>(Wih + (size_t)(kk + k) * G4 + n0 + q * 4);
    };

    loadA(0, 0);
    loadB(0, 0);
    __syncthreads();

    for (int ch = 0; ch < 4; ch++) {
        int s = ch & 1;
        if (ch + 1 < 4) { loadA(s ^ 1, (ch + 1) * 16); loadB(s ^ 1, (ch + 1) * 16); }
#pragma unroll
        for (int k = 0; k < 16; k++) {
            float4 b4 = *reinterpret_cast<const float4*>(&Bs[s][k][tx * 4]);
            float4 a0 = *reinterpret_cast<const float4*>(&As[s][k][ty * 8]);
            float4 a1 = *reinterpret_cast<const float4*>(&As[s][k][ty * 8 + 4]);
            float2 aa[4] = { {a0.x, a0.y}, {a0.z, a0.w}, {a1.x, a1.y}, {a1.z, a1.w} };
            float  bb[4] = { b4.x, b4.y, b4.z, b4.w };
#pragma unroll
            for (int c = 0; c < 4; c++) {
                float2 bv = make_float2(bb[c], bb[c]);
#pragma unroll
                for (int mp = 0; mp < 4; mp++) acc[mp][c] = ffma2(aa[mp], bv, acc[mp][c]);
            }
        }
        __syncthreads();
    }

#pragma unroll
    for (int mp = 0; mp < 4; mp++) {
        float4 r0v, r1v;
        r0v.x = acc[mp][0].x + bsr[0]; r0v.y = acc[mp][1].x + bsr[1];
        r0v.z = acc[mp][2].x + bsr[2]; r0v.w = acc[mp][3].x + bsr[3];
        r1v.x = acc[mp][0].y + bsr[0]; r1v.y = acc[mp][1].y + bsr[1];
        r1v.z = acc[mp][2].y + bsr[2]; r1v.w = acc[mp][3].y + bsr[3];
        int r = row0 + ty * 8 + mp * 2;
        *reinterpret_cast<float4*>(g_gx + (size_t)r * G4 + n0 + tx * 4)       = r0v;
        *reinterpret_cast<float4*>(g_gx + (size_t)(r + 1) * G4 + n0 + tx * 4) = r1v;
    }
}

// ---------------- kernel 3: LSTM (L2-synchronized, cluster-free) ----------------
// 16 logical groups x 8 CTAs x 512 threads. Warp w owns units {2w,2w+1}; lane =
// (gl = type replica, kq = k-eighth). Per step, fully warp-autonomous:
//   poll flag[t-1] (ld.acquire.gpu) -> __ldcg h from g_h (L1-bypass, no stale L1)
//   -> reg GEMM -> butterfly reduce -> type gather -> activation
//   -> gl==0 lanes STG h to g_h[buf] -> __syncwarp -> lane0 red.release flag[t].
__global__ __launch_bounds__(512, 1)
void lstm_kernel(const float* __restrict__ Whh,
                 const float* __restrict__ gx,
                 float* __restrict__ of) {
    extern __shared__ float Ws[];   // 256 x 128 staged W slice

    const int tid  = threadIdx.x;
    const int w    = tid >> 5, lane = tid & 31;
    const int gl   = lane >> 3, kq = lane & 7;
    const int rank = blockIdx.x & 7;
    const int c    = blockIdx.x >> 3;        // group id 0..15
    const int batch0 = c * 4;

    // ---- stage W_hh slice coalesced: Ws[k][lc], lc = type*32 + uloc ----
    for (int i = tid; i < 8192; i += 512) {
        int k = i >> 5, c4 = i & 31;
        int lc = c4 * 4;
        int col = ((lc >> 5) << 8) + (rank << 5) + (lc & 31);
        float4 v4 = *reinterpret_cast<const float4*>(Whh + (size_t)k * G4 + col);
        *reinterpret_cast<float4*>(Ws + k * 128 + lc) = v4;
    }
    __syncthreads();

    // ---- W regs: (type gl, units 2w+j), k in [kq*32, kq*32+32) ----
    float2 Wr[2][16];
#pragma unroll
    for (int j = 0; j < 2; j++) {
        int lc = gl * 32 + 2 * w + j;
#pragma unroll
        for (int m = 0; m < 16; m++) {
            int k = kq * 32 + 2 * m;
            Wr[j][m].x = Ws[k * 128 + lc];
            Wr[j][m].y = Ws[(k + 1) * 128 + lc];
        }
    }

    // per-lane combo identity after reduction
    const int j_c = kq >> 2, b_c = kq & 3;
    const int uloc = 2 * w + j_c;
    const int uglob = (rank << 5) + uloc;

    const float* gxp = gx + (size_t)(batch0 + b_c) * SEQ * G4 + gl * 256 + uglob;
    float* ofp = of + (size_t)(batch0 + b_c) * (SEQ * HID) + uglob;

    float* hout = &g_h[c][0][b_c][uglob];            // +1024 floats for buf 1
    const float4* hbase = reinterpret_cast<const float4*>(&g_h[c][0][0][0]);
    int* flags = &g_flags[c][0];

    float creg = 0.0f;

    for (int t = 0; t < SEQ; t++) {
        const int p = t & 1;
        float gxv = __ldg(gxp);          // independent; overlaps the poll
        float v[8];

        if (t > 0) {
            // ---- wait for all 128 warps of the group to publish h(t-1) ----
            const int* f = flags + (t - 1);
            while (ld_acquire_gpu(f) < 128) { }

            // ---- GEMM from g_h[(t-1)&1] via L1-bypassing loads ----
            const float4* hb = hbase + (p ^ 1) * 256 + kq * 8;   // buf stride 1024 floats
#pragma unroll
            for (int b = 0; b < 4; b++) {
                float4 A[8];
                const float4* hp = hb + b * 64;
#pragma unroll
                for (int i = 0; i < 8; i++) A[i] = __ldcg(hp + i);
                float2 a0 = make_float2(0.f, 0.f), a1 = make_float2(0.f, 0.f);
#pragma unroll
                for (int i = 0; i < 8; i++) {
                    float2 e0 = make_float2(A[i].x, A[i].y);
                    float2 e1 = make_float2(A[i].z, A[i].w);
                    a0 = ffma2(Wr[0][2 * i],     e0, a0);
                    a0 = ffma2(Wr[0][2 * i + 1], e1, a0);
                    a1 = ffma2(Wr[1][2 * i],     e0, a1);
                    a1 = ffma2(Wr[1][2 * i + 1], e1, a1);
                }
                v[b]     = a0.x + a0.y;
                v[4 + b] = a1.x + a1.y;
            }
        } else {
#pragma unroll
            for (int i = 0; i < 8; i++) v[i] = 0.0f;
        }

        // ---- butterfly reduce over 8 kq lanes (combo = kq) ----
        {
            bool up4 = (kq & 4);
#pragma unroll
            for (int i = 0; i < 4; i++) {
                float mine = up4 ? v[i + 4] : v[i];
                float thrs = up4 ? v[i] : v[i + 4];
                v[i] = mine + __shfl_xor_sync(0xffffffffu, thrs, 4);
            }
            bool up2 = (kq & 2);
#pragma unroll
            for (int i = 0; i < 2; i++) {
                float mine = up2 ? v[i + 2] : v[i];
                float thrs = up2 ? v[i] : v[i + 2];
                v[i] = mine + __shfl_xor_sync(0xffffffffu, thrs, 2);
            }
            bool up1 = (kq & 1);
            {
                float mine = up1 ? v[1] : v[0];
                float thrs = up1 ? v[0] : v[1];
                v[0] = mine + __shfl_xor_sync(0xffffffffu, thrs, 1);
            }
        }

        // ---- cross-type gather ----
        float tm = v[0] + gxv;
        float tb = __shfl_xor_sync(0xffffffffu, tm, 8);
        float tc = __shfl_xor_sync(0xffffffffu, tm, 16);
        float td = __shfl_xor_sync(0xffffffffu, tm, 24);

        float gi_ = (gl == 0) ? tm : (gl == 1) ? tb : (gl == 2) ? tc : td;
        float gf_ = (gl == 1) ? tm : (gl == 0) ? tb : (gl == 3) ? tc : td;
        float gg_ = (gl == 2) ? tm : (gl == 3) ? tb : (gl == 0) ? tc : td;
        float go_ = (gl == 3) ? tm : (gl == 2) ? tb : (gl == 1) ? tc : td;

        float tg = tanh_(gg_);
        creg = sigm(gf_) * creg + sigm(gi_) * tg;
        float h = sigm(go_) * tanh_(creg);

        // ---- publish h(t) into g_h[t&1] + arrive on flag[t] ----
        if (gl == 0) {
            hout[p * 1024] = h;
            ofp[(size_t)t * HID] = h;
        }
        __syncwarp();
        if (lane == 0 && t + 1 < SEQ)
            red_release_gpu_add(flags + t, 1);

        gxp += G4;
    }
}

// ---------------- kernel 4: classifier + log_softmax ----------------
__global__ __launch_bounds__(256) void cls_kernel(const float* __restrict__ of,
                                                  const float* __restrict__ W1,
                                                  const float* __restrict__ b1,
                                                  const float* __restrict__ W2,
                                                  const float* __restrict__ b2,
                                                  float* __restrict__ lp) {
    __shared__ float As[2][16][132];
    __shared__ float Bs[2][16][64];

    const int tid = threadIdx.x;
    const int tx = tid & 15, ty = tid >> 4;
    const int row0 = blockIdx.x * 128;

    float b1r[4], w20[4], w21[4];
#pragma unroll
    for (int c = 0; c < 4; c++) {
        int f = tx * 4 + c;
        b1r[c] = b1[f];
        w20[c] = W2[f * 2 + 0];
        w21[c] = W2[f * 2 + 1];
    }
    const float bb0 = b2[0], bb1 = b2[1];

    float2 acc[4][4];
#pragma unroll
    for (int mp = 0; mp < 4; mp++)
#pragma unroll
        for (int c = 0; c < 4; c++) acc[mp][c] = make_float2(0.f, 0.f);

    auto loadA = [&](int s, int kk) {
#pragma unroll
        for (int i = 0; i < 2; i++) {
            int id = tid * 2 + i;
            int m = id >> 2, q = id & 3;
            float4 v = *reinterpret_cast<const float4*>(of + (size_t)(row0 + m) * HID + kk + q * 4);
            As[s][q * 4 + 0][m] = v.x;
            As[s][q * 4 + 1][m] = v.y;
            As[s][q * 4 + 2][m] = v.z;
            As[s][q * 4 + 3][m] = v.w;
        }
    };
    auto loadB = [&](int s, int kk) {
        int k = tid >> 4, q = tid & 15;
        *reinterpret_cast<float4*>(&Bs[s][k][q * 4]) =
            *reinterpret_cast<const float4*>(W1 + (size_t)(kk + k) * 64 + q * 4);
    };

    loadA(0, 0);
    loadB(0, 0);
    __syncthreads();

    for (int ch = 0; ch < 16; ch++) {
        int s = ch & 1;
        if (ch + 1 < 16) { loadA(s ^ 1, (ch + 1) * 16); loadB(s ^ 1, (ch + 1) * 16); }
#pragma unroll
        for (int k = 0; k < 16; k++) {
            float4 b4 = *reinterpret_cast<const float4*>(&Bs[s][k][tx * 4]);
            float4 a0 = *reinterpret_cast<const float4*>(&As[s][k][ty * 8]);
            float4 a1 = *reinterpret_cast<const float4*>(&As[s][k][ty * 8 + 4]);
            float2 aa[4] = { {a0.x, a0.y}, {a0.z, a0.w}, {a1.x, a1.y}, {a1.z, a1.w} };
            float  bb[4] = { b4.x, b4.y, b4.z, b4.w };
#pragma unroll
            for (int c = 0; c < 4; c++) {
                float2 bv = make_float2(bb[c], bb[c]);
#pragma unroll
                for (int mp = 0; mp < 4; mp++) acc[mp][c] = ffma2(aa[mp], bv, acc[mp][c]);
            }
        }
        __syncthreads();
    }

#pragma unroll
    for (int mp = 0; mp < 4; mp++) {
#pragma unroll
        for (int half = 0; half < 2; half++) {
            float p0 = 0.f, p1 = 0.f;
#pragma unroll
            for (int c = 0; c < 4; c++) {
                float vv = half ? acc[mp][c].y : acc[mp][c].x;
                float hd = fmaxf(vv + b1r[c], 0.f);
                p0 += hd * w20[c];
                p1 += hd * w21[c];
            }
#pragma unroll
            for (int s = 1; s < 16; s <<= 1) {
                p0 += __shfl_xor_sync(0xffffffffu, p0, s);
                p1 += __shfl_xor_sync(0xffffffffu, p1, s);
            }
            if ((tid & 15) == 0) {
                float l0 = p0 + bb0, l1 = p1 + bb1;
                float m = fmaxf(l0, l1);
                float lse = m + logf(expf(l0 - m) + expf(l1 - m));
                int row = row0 + ty * 8 + mp * 2 + half;
                lp[row * 2 + 0] = l0 - lse;
                lp[row * 2 + 1] = l1 - lse;
            }
        }
    }
}

// ---------------- kernel 5: gather selected ----------------
__global__ void sel_kernel(const int* __restrict__ ix, const float* __restrict__ of,
                           float* __restrict__ sel) {
    int b = blockIdx.x;
    int t = ix[b];
    sel[b * HID + threadIdx.x] = of[(size_t)b * (SEQ * HID) + (size_t)t * HID + threadIdx.x];
}

// ---------------- launch ----------------
extern "C" void kernel_launch(void* const* d_in, const int* in_sizes, int n_in,
                              void* d_out, int out_size) {
    const float* img = (const float*)d_in[0];
    const float* phr = (const float*)d_in[1];
    const int*   six = (const int*)d_in[3];
    const float* Wc  = (const float*)d_in[4];
    const float* bc  = (const float*)d_in[5];
    const float* Wp  = (const float*)d_in[6];
    const float* bp  = (const float*)d_in[7];
    const float* Wih = (const float*)d_in[8];
    const float* bih = (const float*)d_in[9];
    const float* Whh = (const float*)d_in[10];
    const float* bhh = (const float*)d_in[11];
    const float* W1  = (const float*)d_in[12];
    const float* b1  = (const float*)d_in[13];
    const float* W2  = (const float*)d_in[14];
    const float* b2  = (const float*)d_in[15];

    float* out = (float*)d_out;
    float* lp  = out + OFF_LP;
    float* of  = out + OFF_OF;
    float* sel = out + OFF_SEL;

    float* gxp = nullptr;
    cudaGetSymbolAddress((void**)&gxp, g_gx);

    const int smem_bytes = 32768 * 4;   // 131072
    cudaFuncSetAttribute(lstm_kernel, cudaFuncAttributeMaxDynamicSharedMemorySize, smem_bytes);

    zero_flags_kernel<<<16, 512>>>();
    emb_kernel <<<64, 64>>>(phr, Wp, bp);
    fuse_kernel<<<256, 256>>>(img, Wc, bc);
    gx_kernel  <<<dim3(256, 16), 256>>>(Wih, bih, bhh);
    lstm_kernel<<<128, 512, smem_bytes>>>(Whh, gxp, of);
    cls_kernel <<<256, 256>>>(of, W1, b1, W2, b2, lp);
    sel_kernel <<<64, 256>>>(six, of, sel);
}

// round 8
// speedup vs baseline: 2.0373x; 2.0373x over previous
#include <cuda_runtime.h>
#include <cstdint>
#include <math.h>

// Problem dims
#define NB   64
#define SEQ  512
#define IMG  3200
#define FC   64
#define HID  256
#define G4   1024

// Output layout (floats): [logprobs 64*512*2 | output_feats 64*512*256 | selected 64*256]
#define OFF_LP  0
#define OFF_OF  (NB*SEQ*2)
#define OFF_SEL (OFF_OF + NB*SEQ*HID)

// ---------------- scratch ----------------
__device__ float g_emb[NB * FC];
__device__ float g_fuse[NB * SEQ * FC];
__device__ float g_gx[(size_t)NB * SEQ * G4 + G4];   // +1 row pad for unconditional prefetch

// ---------------- helpers ----------------
__device__ __forceinline__ float2 ffma2(float2 a, float2 b, float2 c) {
    unsigned long long ua = *reinterpret_cast<unsigned long long*>(&a);
    unsigned long long ub = *reinterpret_cast<unsigned long long*>(&b);
    unsigned long long uc = *reinterpret_cast<unsigned long long*>(&c);
    unsigned long long ud;
    asm("fma.rn.f32x2 %0, %1, %2, %3;" : "=l"(ud) : "l"(ua), "l"(ub), "l"(uc));
    return *reinterpret_cast<float2*>(&ud);
}

__device__ __forceinline__ uint32_t smem_u32(const void* p) {
    uint32_t a;
    asm("{ .reg .u64 t; cvta.to.shared.u64 t, %1; cvt.u32.u64 %0, t; }" : "=r"(a) : "l"(p));
    return a;
}

__device__ __forceinline__ float sigm(float x)  { return 1.0f / (1.0f + __expf(-x)); }
__device__ __forceinline__ float tanh_(float x) { return 1.0f - 2.0f / (__expf(2.0f * x) + 1.0f); }

__device__ __forceinline__ void mbar_init(uint32_t a, uint32_t c) {
    asm volatile("mbarrier.init.shared.b64 [%0], %1;" :: "r"(a), "r"(c) : "memory");
}
__device__ __forceinline__ void mbar_expect_tx(uint32_t a, uint32_t tx) {
    asm volatile("mbarrier.arrive.expect_tx.shared.b64 _, [%0], %1;" :: "r"(a), "r"(tx) : "memory");
}
// CTA-scope acquire (R2's proven-fast combination with st.async)
__device__ __forceinline__ void mbar_wait_acq(uint32_t a, uint32_t phase) {
    asm volatile(
        "{\n\t"
        ".reg .pred P;\n\t"
        "WL_%=:\n\t"
        "mbarrier.try_wait.parity.acquire.cta.shared::cta.b64 P, [%0], %1, 0x989680;\n\t"
        "@P bra WD_%=;\n\t"
        "bra WL_%=;\n\t"
        "WD_%=:\n\t"
        "}" :: "r"(a), "r"(phase) : "memory");
}
__device__ __forceinline__ uint32_t mapa_u32(uint32_t a, uint32_t r) {
    uint32_t ra;
    asm("mapa.shared::cluster.u32 %0, %1, %2;" : "=r"(ra) : "r"(a), "r"(r));
    return ra;
}
__device__ __forceinline__ void st_async_f32x2(uint32_t dst, float a, float b, uint32_t rbar) {
    unsigned long long v;
    asm("mov.b64 %0, {%1, %2};" : "=l"(v) : "r"(__float_as_uint(a)), "r"(__float_as_uint(b)));
    asm volatile("st.async.shared::cluster.mbarrier::complete_tx::bytes.b64 [%0], %1, [%2];"
                 :: "r"(dst), "l"(v), "r"(rbar) : "memory");
}

// ---------------- kernel 1: emb ----------------
__global__ void emb_kernel(const float* __restrict__ phr,
                           const float* __restrict__ Wp,
                           const float* __restrict__ bp) {
    __shared__ float ps[304];
    int b = blockIdx.x, tid = threadIdx.x;
    for (int i = tid; i < 300; i += 64) ps[i] = phr[b * 300 + i];
    __syncthreads();
    float acc = bp[tid];
#pragma unroll 4
    for (int k = 0; k < 300; k++) acc += ps[k] * Wp[k * 64 + tid];
    g_emb[b * 64 + tid] = fmaxf(acc, 0.0f);
}

// ---------------- kernel 2: fuse ----------------
__global__ __launch_bounds__(256) void fuse_kernel(const float* __restrict__ img,
                                                   const float* __restrict__ Wc,
                                                   const float* __restrict__ bc) {
    __shared__ float As[2][16][132];
    __shared__ float Bs[2][16][64];
    __shared__ float es[64];

    const int tid = threadIdx.x;
    const int tx = tid & 15, ty = tid >> 4;
    const int row0 = blockIdx.x * 128;
    const int batch = row0 >> 9;

    if (tid < 64) es[tid] = g_emb[batch * 64 + tid];

    float bcr[4];
#pragma unroll
    for (int c = 0; c < 4; c++) bcr[c] = bc[tx * 4 + c];

    float2 acc[4][4];
#pragma unroll
    for (int mp = 0; mp < 4; mp++)
#pragma unroll
        for (int c = 0; c < 4; c++) acc[mp][c] = make_float2(0.f, 0.f);

    auto loadA = [&](int s, int kk) {
#pragma unroll
        for (int i = 0; i < 2; i++) {
            int id = tid * 2 + i;
            int m = id >> 2, q = id & 3;
            float4 v = *reinterpret_cast<const float4*>(img + (size_t)(row0 + m) * IMG + kk + q * 4);
            As[s][q * 4 + 0][m] = v.x;
            As[s][q * 4 + 1][m] = v.y;
            As[s][q * 4 + 2][m] = v.z;
            As[s][q * 4 + 3][m] = v.w;
        }
    };
    auto loadB = [&](int s, int kk) {
        int k = tid >> 4, q = tid & 15;
        *reinterpret_cast<float4*>(&Bs[s][k][q * 4]) =
            *reinterpret_cast<const float4*>(Wc + (size_t)(kk + k) * 64 + q * 4);
    };

    loadA(0, 0);
    loadB(0, 0);
    __syncthreads();

    for (int ch = 0; ch < 200; ch++) {
        int s = ch & 1;
        if (ch + 1 < 200) { loadA(s ^ 1, (ch + 1) * 16); loadB(s ^ 1, (ch + 1) * 16); }
#pragma unroll
        for (int k = 0; k < 16; k++) {
            float4 b4 = *reinterpret_cast<const float4*>(&Bs[s][k][tx * 4]);
            float4 a0 = *reinterpret_cast<const float4*>(&As[s][k][ty * 8]);
            float4 a1 = *reinterpret_cast<const float4*>(&As[s][k][ty * 8 + 4]);
            float2 aa[4] = { {a0.x, a0.y}, {a0.z, a0.w}, {a1.x, a1.y}, {a1.z, a1.w} };
            float  bb[4] = { b4.x, b4.y, b4.z, b4.w };
#pragma unroll
            for (int c = 0; c < 4; c++) {
                float2 bv = make_float2(bb[c], bb[c]);
#pragma unroll
                for (int mp = 0; mp < 4; mp++) acc[mp][c] = ffma2(aa[mp], bv, acc[mp][c]);
            }
        }
        __syncthreads();
    }

    float sc[4];
#pragma unroll
    for (int c = 0; c < 4; c++) sc[c] = es[tx * 4 + c];

#pragma unroll
    for (int mp = 0; mp < 4; mp++) {
        float4 r0v, r1v;
        r0v.x = fmaxf(acc[mp][0].x + bcr[0], 0.f) * sc[0];
        r0v.y = fmaxf(acc[mp][1].x + bcr[1], 0.f) * sc[1];
        r0v.z = fmaxf(acc[mp][2].x + bcr[2], 0.f) * sc[2];
        r0v.w = fmaxf(acc[mp][3].x + bcr[3], 0.f) * sc[3];
        r1v.x = fmaxf(acc[mp][0].y + bcr[0], 0.f) * sc[0];
        r1v.y = fmaxf(acc[mp][1].y + bcr[1], 0.f) * sc[1];
        r1v.z = fmaxf(acc[mp][2].y + bcr[2], 0.f) * sc[2];
        r1v.w = fmaxf(acc[mp][3].y + bcr[3], 0.f) * sc[3];
        int r = row0 + ty * 8 + mp * 2;
        *reinterpret_cast<float4*>(g_fuse + (size_t)r * 64 + tx * 4)       = r0v;
        *reinterpret_cast<float4*>(g_fuse + (size_t)(r + 1) * 64 + tx * 4) = r1v;
    }
}

// ---------------- kernel 2b: gx = fuse @ W_ih + (b_ih + b_hh) ----------------
__global__ __launch_bounds__(256) void gx_kernel(const float* __restrict__ Wih,
                                                 const float* __restrict__ bih,
                                                 const float* __restrict__ bhh) {
    __shared__ float As[2][16][132];
    __shared__ float Bs[2][16][64];

    const int tid = threadIdx.x;
    const int tx = tid & 15, ty = tid >> 4;
    const int row0 = blockIdx.x * 128;
    const int n0 = blockIdx.y * 64;

    float bsr[4];
#pragma unroll
    for (int c = 0; c < 4; c++) bsr[c] = bih[n0 + tx * 4 + c] + bhh[n0 + tx * 4 + c];

    float2 acc[4][4];
#pragma unroll
    for (int mp = 0; mp < 4; mp++)
#pragma unroll
        for (int c = 0; c < 4; c++) acc[mp][c] = make_float2(0.f, 0.f);

    auto loadA = [&](int s, int kk) {
#pragma unroll
        for (int i = 0; i < 2; i++) {
            int id = tid * 2 + i;
            int m = id >> 2, q = id & 3;
            float4 v = *reinterpret_cast<const float4*>(g_fuse + (size_t)(row0 + m) * FC + kk + q * 4);
            As[s][q * 4 + 0][m] = v.x;
            As[s][q * 4 + 1][m] = v.y;
            As[s][q * 4 + 2][m] = v.z;
            As[s][q * 4 + 3][m] = v.w;
        }
    };
    auto loadB = [&](int s, int kk) {
        int k = tid >> 4, q = tid & 15;
        *reinterpret_cast<float4*>(&Bs[s][k][q * 4]) =
            *reinterpret_cast<const float4*>(Wih + (size_t)(kk + k) * G4 + n0 + q * 4);
    };

    loadA(0, 0);
    loadB(0, 0);
    __syncthreads();

    for (int ch = 0; ch < 4; ch++) {
        int s = ch & 1;
        if (ch + 1 < 4) { loadA(s ^ 1, (ch + 1) * 16); loadB(s ^ 1, (ch + 1) * 16); }
#pragma unroll
        for (int k = 0; k < 16; k++) {
            float4 b4 = *reinterpret_cast<const float4*>(&Bs[s][k][tx * 4]);
            float4 a0 = *reinterpret_cast<const float4*>(&As[s][k][ty * 8]);
            float4 a1 = *reinterpret_cast<const float4*>(&As[s][k][ty * 8 + 4]);
            float2 aa[4] = { {a0.x, a0.y}, {a0.z, a0.w}, {a1.x, a1.y}, {a1.z, a1.w} };
            float  bb[4] = { b4.x, b4.y, b4.z, b4.w };
#pragma unroll
            for (int c = 0; c < 4; c++) {
                float2 bv = make_float2(bb[c], bb[c]);
#pragma unroll
                for (int mp = 0; mp < 4; mp++) acc[mp][c] = ffma2(aa[mp], bv, acc[mp][c]);
            }
        }
        __syncthreads();
    }

#pragma unroll
    for (int mp = 0; mp < 4; mp++) {
        float4 r0v, r1v;
        r0v.x = acc[mp][0].x + bsr[0]; r0v.y = acc[mp][1].x + bsr[1];
        r0v.z = acc[mp][2].x + bsr[2]; r0v.w = acc[mp][3].x + bsr[3];
        r1v.x = acc[mp][0].y + bsr[0]; r1v.y = acc[mp][1].y + bsr[1];
        r1v.z = acc[mp][2].y + bsr[2]; r1v.w = acc[mp][3].y + bsr[3];
        int r = row0 + ty * 8 + mp * 2;
        *reinterpret_cast<float4*>(g_gx + (size_t)r * G4 + n0 + tx * 4)       = r0v;
        *reinterpret_cast<float4*>(g_gx + (size_t)(r + 1) * G4 + n0 + tx * 4) = r1v;
    }
}

// ---------------- kernel 3: LSTM ----------------
// 16 clusters x 8 CTAs x 512 threads. Warp w owns units {2w,2w+1}; lane =
// (gl = type replica, kq = k-eighth; combo after reduce: j_c = kq>>2, b_c = kq&3).
// Warp-local GEMM/reduce/activation. h exchange: shfl_xor(4) pairs units, only
// j_c==0 lanes send st.async.b64 (unit pair) to their 2 peers -> 512 msgs/CTA/step.
// Wait is .acquire.cta (R2's proven combination). gx double-buffered in registers.
#define HB_B    288                   // floats per (buf,b): 8 chunks * 36
#define HB_BUF  1152                  // floats per buf
#define HB_BUF_BYTES (HB_BUF * 4)     // 4608

__global__ void __cluster_dims__(8, 1, 1) __launch_bounds__(512, 1)
lstm_kernel(const float* __restrict__ Whh,
            const float* __restrict__ gx,
            float* __restrict__ of) {
    extern __shared__ float sm[];
    unsigned long long* bars = (unsigned long long*)sm;   // 2 x u64
    float* hbuf = sm + 4;                                 // 2*1152 floats
    float* Ws   = hbuf + 2304;                            // 256*128 staged W slice

    const int tid  = threadIdx.x;
    const int w    = tid >> 5, lane = tid & 31;
    const int gl   = lane >> 3, kq = lane & 7;
    const int rank   = blockIdx.x & 7;
    const int batch0 = (blockIdx.x >> 3) * 4;

    // ---- stage W_hh slice coalesced: Ws[k][lc], lc = type*32 + uloc ----
    for (int i = tid; i < 8192; i += 512) {
        int k = i >> 5, c4 = i & 31;
        int lc = c4 * 4;
        int col = ((lc >> 5) << 8) + (rank << 5) + (lc & 31);
        float4 v4 = *reinterpret_cast<const float4*>(Whh + (size_t)k * G4 + col);
        *reinterpret_cast<float4*>(Ws + k * 128 + lc) = v4;
    }
    const uint32_t bar0 = smem_u32(bars);
    if (tid == 0) {
        mbar_init(bar0, 1);
        mbar_init(bar0 + 8, 1);
        mbar_expect_tx(bar0, 4096);      // first use: t=2 (buffer 0)
        mbar_expect_tx(bar0 + 8, 4096);  // first use: t=1 (buffer 1)
    }
    __syncthreads();

    // ---- W regs: (type gl, units 2w+j), k in [kq*32, kq*32+32) ----
    float2 Wr[2][16];
#pragma unroll
    for (int j = 0; j < 2; j++) {
        int lc = gl * 32 + 2 * w + j;
#pragma unroll
        for (int m = 0; m < 16; m++) {
            int k = kq * 32 + 2 * m;
            Wr[j][m].x = Ws[k * 128 + lc];
            Wr[j][m].y = Ws[(k + 1) * 128 + lc];
        }
    }

    asm volatile("barrier.cluster.arrive.aligned;" ::: "memory");
    asm volatile("barrier.cluster.wait.aligned;"   ::: "memory");

    // per-lane combo identity after reduction
    const int j_c = kq >> 2, b_c = kq & 3;
    const int uloc = 2 * w + j_c;
    const int uglob = (rank << 5) + uloc;

    const float* gxp = gx + (size_t)(batch0 + b_c) * SEQ * G4 + gl * 256 + uglob;
    float* ofp = of + (size_t)(batch0 + b_c) * (SEQ * HID) + uglob;

    // send base: unit-pair (2w, 2w+1), batch b_c -> chunk index is `rank` (2w < 32)
    uint32_t dst_loc = smem_u32(hbuf + b_c * HB_B + rank * 36 + 2 * w);
    uint32_t pd0 = mapa_u32(dst_loc, 2 * gl);
    uint32_t pd1 = mapa_u32(dst_loc, 2 * gl + 1);
    uint32_t pb0 = mapa_u32(bar0, 2 * gl);
    uint32_t pb1 = mapa_u32(bar0, 2 * gl + 1);

    float creg = 0.0f;
    int ph0 = 0, ph1 = 0;
    float gxv = __ldg(gxp);          // value for t=0

    for (int t = 0; t < SEQ; t++) {
        const int p = t & 1;
        float gxn = __ldg(gxp + G4); // prefetch t+1 a full step ahead (array padded)
        float v[8];

        if (t > 0) {
            uint32_t barp = bar0 + p * 8;
            int par = p ? ph1 : ph0;
            mbar_wait_acq(barp, par);
            if (p) ph1 ^= 1; else ph0 ^= 1;
            if (tid == 0) mbar_expect_tx(barp, 4096);   // re-arm for t+2

#pragma unroll
            for (int b = 0; b < 4; b++) {
                const float* hp = hbuf + p * HB_BUF + b * HB_B + kq * 36;
                float2 a0 = make_float2(0.f, 0.f), a1 = make_float2(0.f, 0.f);
#pragma unroll
                for (int i = 0; i < 8; i++) {
                    float4 hh = *reinterpret_cast<const float4*>(hp + 4 * i);
                    float2 e0 = make_float2(hh.x, hh.y);
                    float2 e1 = make_float2(hh.z, hh.w);
                    a0 = ffma2(Wr[0][2 * i],     e0, a0);
                    a0 = ffma2(Wr[0][2 * i + 1], e1, a0);
                    a1 = ffma2(Wr[1][2 * i],     e0, a1);
                    a1 = ffma2(Wr[1][2 * i + 1], e1, a1);
                }
                v[b]     = a0.x + a0.y;
                v[4 + b] = a1.x + a1.y;
            }
        } else {
#pragma unroll
            for (int i = 0; i < 8; i++) v[i] = 0.0f;
        }

        // ---- butterfly reduce over 8 kq lanes (combo = kq) ----
        {
            bool up4 = (kq & 4);
#pragma unroll
            for (int i = 0; i < 4; i++) {
                float mine = up4 ? v[i + 4] : v[i];
                float thrs = up4 ? v[i] : v[i + 4];
                v[i] = mine + __shfl_xor_sync(0xffffffffu, thrs, 4);
            }
            bool up2 = (kq & 2);
#pragma unroll
            for (int i = 0; i < 2; i++) {
                float mine = up2 ? v[i + 2] : v[i];
                float thrs = up2 ? v[i] : v[i + 2];
                v[i] = mine + __shfl_xor_sync(0xffffffffu, thrs, 2);
            }
            bool up1 = (kq & 1);
            {
                float mine = up1 ? v[1] : v[0];
                float thrs = up1 ? v[0] : v[1];
                v[0] = mine + __shfl_xor_sync(0xffffffffu, thrs, 1);
            }
        }

        // ---- cross-type gather ----
        float tm = v[0] + gxv;
        float tb = __shfl_xor_sync(0xffffffffu, tm, 8);
        float tc = __shfl_xor_sync(0xffffffffu, tm, 16);
        float td = __shfl_xor_sync(0xffffffffu, tm, 24);

        float gi_ = (gl == 0) ? tm : (gl == 1) ? tb : (gl == 2) ? tc : td;
        float gf_ = (gl == 1) ? tm : (gl == 0) ? tb : (gl == 3) ? tc : td;
        float gg_ = (gl == 2) ? tm : (gl == 3) ? tb : (gl == 0) ? tc : td;
        float go_ = (gl == 3) ? tm : (gl == 2) ? tb : (gl == 1) ? tc : td;

        float tg = tanh_(gg_);
        creg = sigm(gf_) * creg + sigm(gi_) * tg;
        float h = sigm(go_) * tanh_(creg);

        // ---- pair units (2w, 2w+1) and send 8B packets ----
        float ho = __shfl_xor_sync(0xffffffffu, h, 4);   // partner j_c
        if (t + 1 < SEQ && (lane & 4) == 0) {            // j_c == 0 lanes send
            uint32_t doff = (uint32_t)((p ^ 1) * HB_BUF_BYTES);
            uint32_t boff = (uint32_t)((p ^ 1) * 8);
            st_async_f32x2(pd0 + doff, h, ho, pb0 + boff);
            st_async_f32x2(pd1 + doff, h, ho, pb1 + boff);
        }
        if (gl == 0) ofp[(size_t)t * HID] = h;

        gxv = gxn;
        gxp += G4;
    }

    asm volatile("barrier.cluster.arrive.aligned;" ::: "memory");
    asm volatile("barrier.cluster.wait.aligned;"   ::: "memory");
}

// ---------------- kernel 4: classifier + log_softmax ----------------
__global__ __launch_bounds__(256) void cls_kernel(const float* __restrict__ of,
                                                  const float* __restrict__ W1,
                                                  const float* __restrict__ b1,
                                                  const float* __restrict__ W2,
                                                  const float* __restrict__ b2,
                                                  float* __restrict__ lp) {
    __shared__ float As[2][16][132];
    __shared__ float Bs[2][16][64];

    const int tid = threadIdx.x;
    const int tx = tid & 15, ty = tid >> 4;
    const int row0 = blockIdx.x * 128;

    float b1r[4], w20[4], w21[4];
#pragma unroll
    for (int c = 0; c < 4; c++) {
        int f = tx * 4 + c;
        b1r[c] = b1[f];
        w20[c] = W2[f * 2 + 0];
        w21[c] = W2[f * 2 + 1];
    }
    const float bb0 = b2[0], bb1 = b2[1];

    float2 acc[4][4];
#pragma unroll
    for (int mp = 0; mp < 4; mp++)
#pragma unroll
        for (int c = 0; c < 4; c++) acc[mp][c] = make_float2(0.f, 0.f);

    auto loadA = [&](int s, int kk) {
#pragma unroll
        for (int i = 0; i < 2; i++) {
            int id = tid * 2 + i;
            int m = id >> 2, q = id & 3;
            float4 v = *reinterpret_cast<const float4*>(of + (size_t)(row0 + m) * HID + kk + q * 4);
            As[s][q * 4 + 0][m] = v.x;
            As[s][q * 4 + 1][m] = v.y;
            As[s][q * 4 + 2][m] = v.z;
            As[s][q * 4 + 3][m] = v.w;
        }
    };
    auto loadB = [&](int s, int kk) {
        int k = tid >> 4, q = tid & 15;
        *reinterpret_cast<float4*>(&Bs[s][k][q * 4]) =
            *reinterpret_cast<const float4*>(W1 + (size_t)(kk + k) * 64 + q * 4);
    };

    loadA(0, 0);
    loadB(0, 0);
    __syncthreads();

    for (int ch = 0; ch < 16; ch++) {
        int s = ch & 1;
        if (ch + 1 < 16) { loadA(s ^ 1, (ch + 1) * 16); loadB(s ^ 1, (ch + 1) * 16); }
#pragma unroll
        for (int k = 0; k < 16; k++) {
            float4 b4 = *reinterpret_cast<const float4*>(&Bs[s][k][tx * 4]);
            float4 a0 = *reinterpret_cast<const float4*>(&As[s][k][ty * 8]);
            float4 a1 = *reinterpret_cast<const float4*>(&As[s][k][ty * 8 + 4]);
            float2 aa[4] = { {a0.x, a0.y}, {a0.z, a0.w}, {a1.x, a1.y}, {a1.z, a1.w} };
            float  bb[4] = { b4.x, b4.y, b4.z, b4.w };
#pragma unroll
            for (int c = 0; c < 4; c++) {
                float2 bv = make_float2(bb[c], bb[c]);
#pragma unroll
                for (int mp = 0; mp < 4; mp++) acc[mp][c] = ffma2(aa[mp], bv, acc[mp][c]);
            }
        }
        __syncthreads();
    }

#pragma unroll
    for (int mp = 0; mp < 4; mp++) {
#pragma unroll
        for (int half = 0; half < 2; half++) {
            float p0 = 0.f, p1 = 0.f;
#pragma unroll
            for (int c = 0; c < 4; c++) {
                float vv = half ? acc[mp][c].y : acc[mp][c].x;
                float hd = fmaxf(vv + b1r[c], 0.f);
                p0 += hd * w20[c];
                p1 += hd * w21[c];
            }
#pragma unroll
            for (int s = 1; s < 16; s <<= 1) {
                p0 += __shfl_xor_sync(0xffffffffu, p0, s);
                p1 += __shfl_xor_sync(0xffffffffu, p1, s);
            }
            if ((tid & 15) == 0) {
                float l0 = p0 + bb0, l1 = p1 + bb1;
                float m = fmaxf(l0, l1);
                float lse = m + logf(expf(l0 - m) + expf(l1 - m));
                int row = row0 + ty * 8 + mp * 2 + half;
                lp[row * 2 + 0] = l0 - lse;
                lp[row * 2 + 1] = l1 - lse;
            }
        }
    }
}

// ---------------- kernel 5: gather selected ----------------
__global__ void sel_kernel(const int* __restrict__ ix, const float* __restrict__ of,
                           float* __restrict__ sel) {
    int b = blockIdx.x;
    int t = ix[b];
    sel[b * HID + threadIdx.x] = of[(size_t)b * (SEQ * HID) + (size_t)t * HID + threadIdx.x];
}

// ---------------- launch ----------------
extern "C" void kernel_launch(void* const* d_in, const int* in_sizes, int n_in,
                              void* d_out, int out_size) {
    const float* img = (const float*)d_in[0];
    const float* phr = (const float*)d_in[1];
    const int*   six = (const int*)d_in[3];
    const float* Wc  = (const float*)d_in[4];
    const float* bc  = (const float*)d_in[5];
    const float* Wp  = (const float*)d_in[6];
    const float* bp  = (const float*)d_in[7];
    const float* Wih = (const float*)d_in[8];
    const float* bih = (const float*)d_in[9];
    const float* Whh = (const float*)d_in[10];
    const float* bhh = (const float*)d_in[11];
    const float* W1  = (const float*)d_in[12];
    const float* b1  = (const float*)d_in[13];
    const float* W2  = (const float*)d_in[14];
    const float* b2  = (const float*)d_in[15];

    float* out = (float*)d_out;
    float* lp  = out + OFF_LP;
    float* of  = out + OFF_OF;
    float* sel = out + OFF_SEL;

    float* gxp = nullptr;
    cudaGetSymbolAddress((void**)&gxp, g_gx);

    const int smem_bytes = (4 + 2304 + 32768) * 4;   // 140304
    cudaFuncSetAttribute(lstm_kernel, cudaFuncAttributeMaxDynamicSharedMemorySize, smem_bytes);

    emb_kernel <<<64, 64>>>(phr, Wp, bp);
    fuse_kernel<<<256, 256>>>(img, Wc, bc);
    gx_kernel  <<<dim3(256, 16), 256>>>(Wih, bih, bhh);
    lstm_kernel<<<128, 512, smem_bytes>>>(Whh, gxp, of);
    cls_kernel <<<256, 256>>>(of, W1, b1, W2, b2, lp);
    sel_kernel <<<64, 256>>>(six, of, sel);
}